// round 16
// baseline (speedup 1.0000x reference)
#include <cuda_runtime.h>
#include <cuda_bf16.h>
#include <cuda_fp16.h>
#include <cstdint>
#include <math.h>

#define Bb 2
#define Tt 2048
#define Cc 1024
#define NH 16
#define HD 64
#define MROWS (Bb*Tt)          // 4096
#define QKV_N (3*Cc)           // 3072

// Scratch
__device__ __half g_xn  [MROWS*Cc];            // LN out single fp16
__device__ __half g_wq  [Cc*QKV_N];            // qkv W single fp16
__device__ __half g_wp  [Cc*Cc];               // proj W single fp16
__device__ __half g_q  [Bb*NH*Tt*HD];          // [b,h,t,d] single (scaled 1/8)
__device__ __half g_k  [Bb*NH*Tt*HD];          // [b,h,t,d] single
__device__ __half g_v  [Bb*NH*Tt*HD];          // [b,h,t,d] single
__device__ __half g_att[MROWS*Cc];             // attention out single fp16

__device__ __forceinline__ uint32_t smem_u32(const void* p) {
    return (uint32_t)__cvta_generic_to_shared(p);
}
__device__ __forceinline__ void cp16(uint32_t dst, const void* src) {
    asm volatile("cp.async.ca.shared.global [%0], [%1], 16;\n" :: "r"(dst), "l"(src));
}
__device__ __forceinline__ void cp_commit() { asm volatile("cp.async.commit_group;\n"); }
template<int N> __device__ __forceinline__ void cp_wait() {
    asm volatile("cp.async.wait_group %0;\n" :: "n"(N));
}
__device__ __forceinline__ void ldsm_x4(uint32_t a[4], uint32_t addr) {
    asm volatile("ldmatrix.sync.aligned.m8n8.x4.shared.b16 {%0,%1,%2,%3}, [%4];"
                 : "=r"(a[0]),"=r"(a[1]),"=r"(a[2]),"=r"(a[3]) : "r"(addr));
}
__device__ __forceinline__ void ldsm_x4t(uint32_t b[4], uint32_t addr) {
    asm volatile("ldmatrix.sync.aligned.m8n8.x4.trans.shared.b16 {%0,%1,%2,%3}, [%4];"
                 : "=r"(b[0]),"=r"(b[1]),"=r"(b[2]),"=r"(b[3]) : "r"(addr));
}
__device__ __forceinline__ void mma_f16(float c[4], const uint32_t a[4], const uint32_t b0, const uint32_t b1) {
    asm volatile("mma.sync.aligned.m16n8k16.row.col.f32.f16.f16.f32 "
        "{%0,%1,%2,%3}, {%4,%5,%6,%7}, {%8,%9}, {%0,%1,%2,%3};"
        : "+f"(c[0]),"+f"(c[1]),"+f"(c[2]),"+f"(c[3])
        : "r"(a[0]),"r"(a[1]),"r"(a[2]),"r"(a[3]), "r"(b0),"r"(b1));
}
__device__ __forceinline__ uint32_t pack_hf2(float x, float y) {
    __half2 t = __floats2half2_rn(x, y);
    return *reinterpret_cast<uint32_t*>(&t);
}

// ---------------------------------------------------------------------------
// LayerNorm, warp-per-row: 8 rows per 256-thread block.
// ---------------------------------------------------------------------------
__global__ __launch_bounds__(256) void ln_kernel(
    const float* __restrict__ x, const float* __restrict__ scale,
    const float* __restrict__ bias) {
    const int w = threadIdx.x >> 5, lane = threadIdx.x & 31;
    const int row = blockIdx.x * 8 + w;
    const float* xr = x + (size_t)row * Cc;

    float v[32];
    #pragma unroll
    for (int i = 0; i < 8; i++) {
        float4 t = *reinterpret_cast<const float4*>(xr + i * 128 + lane * 4);
        v[i*4+0] = t.x; v[i*4+1] = t.y; v[i*4+2] = t.z; v[i*4+3] = t.w;
    }
    float s = 0.f;
    #pragma unroll
    for (int i = 0; i < 32; i++) s += v[i];
    #pragma unroll
    for (int o = 16; o > 0; o >>= 1) s += __shfl_xor_sync(0xffffffffu, s, o);
    float mu = s * (1.f / Cc);
    float sq = 0.f;
    #pragma unroll
    for (int i = 0; i < 32; i++) { float d = v[i] - mu; sq += d * d; }
    #pragma unroll
    for (int o = 16; o > 0; o >>= 1) sq += __shfl_xor_sync(0xffffffffu, sq, o);
    float inv = rsqrtf(sq * (1.f / Cc) + 1e-6f);

    #pragma unroll
    for (int i = 0; i < 8; i++) {
        int col = i * 128 + lane * 4;
        float4 sc = *reinterpret_cast<const float4*>(scale + col);
        float4 bi = *reinterpret_cast<const float4*>(bias + col);
        float o0 = (v[i*4+0] - mu) * inv * sc.x + bi.x;
        float o1 = (v[i*4+1] - mu) * inv * sc.y + bi.y;
        float o2 = (v[i*4+2] - mu) * inv * sc.z + bi.z;
        float o3 = (v[i*4+3] - mu) * inv * sc.w + bi.w;
        uint2 pk;
        pk.x = pack_hf2(o0, o1);
        pk.y = pack_hf2(o2, o3);
        *reinterpret_cast<uint2*>(&g_xn[(size_t)row * Cc + col]) = pk;
    }
}

// ---------------------------------------------------------------------------
// fp32 -> fp16 single (weights)
// ---------------------------------------------------------------------------
__global__ __launch_bounds__(256) void cvt_kernel(
    const float* __restrict__ src, __half* __restrict__ dst) {
    int i = (blockIdx.x * 256 + threadIdx.x) * 4;
    float4 v = *reinterpret_cast<const float4*>(src + i);
    *reinterpret_cast<__half2*>(&dst[i])     = __floats2half2_rn(v.x, v.y);
    *reinterpret_cast<__half2*>(&dst[i + 2]) = __floats2half2_rn(v.z, v.w);
}

// ---------------------------------------------------------------------------
// fp16 single tensor-core GEMM: 128x128 block, BK=64, 3-stage cp.async.
// Stage: A[128][72]=9216 + B[64][136]=8704 = 17920 elems (35.8KB) x3.
// ---------------------------------------------------------------------------
#define STAGE_E 17920
#define A_STR 72
#define B_STR 136
#define NCHUNK 16

template<int ND, int EPI>
__global__ __launch_bounds__(256, 2) void mma_gemm(
    const __half* __restrict__ A_g, const __half* __restrict__ B_g,
    const float* __restrict__ bias, float* __restrict__ Cout)
{
    extern __shared__ __half smem[];
    const int tid = threadIdx.x;
    const int wid = tid >> 5, lane = tid & 31;
    const int wm = wid >> 2, wn = wid & 3;
    const int row0 = blockIdx.y * 128;
    const int col0 = blockIdx.x * 128;

    const int laneRowA = (lane & 7) + ((lane >> 3) & 1) * 8;
    const int laneColA = (lane >> 4) * 8;
    const int lb16 = lane & 15;
    const int lbc = (lane >> 4) * 8;

    auto issue = [&](int it, int stage) {
        const int k0 = it * 64;
        __half* s = smem + stage * STAGE_E;
        #pragma unroll
        for (int u = 0; u < 4; u++) {
            int c = tid + u * 256;
            int ar = c >> 3, ac = (c & 7) * 8;          // A: 128 rows x 8 chunks
            cp16(smem_u32(s + ar * A_STR + ac),
                 A_g + (size_t)(row0 + ar) * Cc + k0 + ac);
            int br = c >> 4, bc = (c & 15) * 8;         // B: 64 rows x 16 chunks
            cp16(smem_u32(s + 9216 + br * B_STR + bc),
                 B_g + (size_t)(k0 + br) * ND + col0 + bc);
        }
        cp_commit();
    };

    float acc[4][4][4] = {};
    issue(0, 0);
    issue(1, 1);

    int buf = 0;
    #pragma unroll 1
    for (int it = 0; it < NCHUNK; it++) {
        if (it + 2 < NCHUNK) { issue(it + 2, (it + 2) % 3); cp_wait<2>(); }
        else if (it + 1 < NCHUNK) { cp_wait<1>(); }
        else { cp_wait<0>(); }
        __syncthreads();
        __half* sA = smem + buf * STAGE_E;
        __half* sB = sA + 9216;
        #pragma unroll
        for (int kk = 0; kk < 4; kk++) {
            uint32_t aa[4][4], bb[2][4];
            #pragma unroll
            for (int i = 0; i < 4; i++) {
                int r = wm * 64 + i * 16 + laneRowA;
                int cA = kk * 16 + laneColA;
                ldsm_x4(aa[i], smem_u32(sA + r * A_STR + cA));
            }
            #pragma unroll
            for (int jp = 0; jp < 2; jp++) {
                int rB = kk * 16 + lb16;
                int cB = wn * 32 + jp * 16 + lbc;
                ldsm_x4t(bb[jp], smem_u32(sB + rB * B_STR + cB));
            }
            #pragma unroll
            for (int i = 0; i < 4; i++)
                #pragma unroll
                for (int j = 0; j < 4; j++)
                    mma_f16(acc[i][j], aa[i], bb[j >> 1][(j & 1) * 2],
                            bb[j >> 1][(j & 1) * 2 + 1]);
        }
        __syncthreads();
        buf = (buf + 1) % 3;
    }

    #pragma unroll
    for (int i = 0; i < 4; i++) {
        int rbase = row0 + wm * 64 + i * 16 + (lane >> 2);
        #pragma unroll
        for (int j = 0; j < 4; j++) {
            int nb = col0 + wn * 32 + j * 8 + (lane & 3) * 2;
            float v0 = acc[i][j][0] + bias[nb];
            float v1 = acc[i][j][1] + bias[nb + 1];
            float v2 = acc[i][j][2] + bias[nb];
            float v3 = acc[i][j][3] + bias[nb + 1];
            if (EPI == 1) {
                float2 p0 = {v0, v1}, p1 = {v2, v3};
                *reinterpret_cast<float2*>(&Cout[(size_t)rbase * Cc + nb]) = p0;
                *reinterpret_cast<float2*>(&Cout[(size_t)(rbase + 8) * Cc + nb]) = p1;
            } else {
                int b = rbase >> 11, t = rbase & 2047;
                int which = nb >> 10, rr = nb & 1023;
                int h = rr >> 6, d = rr & 63;
                float sc = (which == 0) ? 0.125f : 1.f;
                __half* dst = (which == 0) ? g_q : ((which == 1) ? g_k : g_v);
                size_t idx = (((size_t)(b * NH + h) * Tt) + t) * HD + d;
                *reinterpret_cast<__half2*>(&dst[idx]) =
                    __floats2half2_rn(v0 * sc, v1 * sc);
                *reinterpret_cast<__half2*>(&dst[idx + 8 * HD]) =
                    __floats2half2_rn(v2 * sc, v3 * sc);
            }
        }
    }
}

// ---------------------------------------------------------------------------
// Tensor-core causal flash attention, fp16, BQ=64, 128 threads (unchanged).
// ---------------------------------------------------------------------------
#define FSTR 72
#define FSTAGE 9216

__global__ __launch_bounds__(128, 4) void flash_mma() {
    extern __shared__ __half fsm[];
    const int tid = threadIdx.x;
    const int w = tid >> 5, lane = tid & 31;
    const int qb = (int)gridDim.x - 1 - (int)blockIdx.x;
    const int bh = blockIdx.y;
    const int q0 = qb * 64;

    const __half* Q_g = g_q + (size_t)bh * Tt * HD;
    const __half* K_g = g_k + (size_t)bh * Tt * HD;
    const __half* V_g = g_v + (size_t)bh * Tt * HD;

    const int laneRowA = (lane & 7) + ((lane >> 3) & 1) * 8;
    const int laneColA = (lane >> 4) * 8;
    const int lb16 = lane & 15;
    const int lbc = (lane >> 4) * 8;

    {
        #pragma unroll
        for (int u = 0; u < 4; u++) {
            int idx = tid + u * 128;
            int r = idx >> 3, c = (idx & 7) * 8;
            cp16(smem_u32(fsm + r * FSTR + c), Q_g + (size_t)(q0 + r) * HD + c);
        }
        cp_commit();
        cp_wait<0>();
        __syncthreads();
    }
    uint32_t qf[4][4];
    #pragma unroll
    for (int kk = 0; kk < 4; kk++) {
        int r = w * 16 + laneRowA;
        int c = kk * 16 + laneColA;
        ldsm_x4(qf[kk], smem_u32(fsm + r * FSTR + c));
    }
    __syncthreads();

    auto issueKV = [&](int kt, int stage) {
        const int k0 = kt * 64;
        __half* s = fsm + stage * FSTAGE;
        #pragma unroll
        for (int u = 0; u < 4; u++) {
            int idx = tid + u * 128;
            int r = idx >> 3, c = (idx & 7) * 8;
            cp16(smem_u32(s + r * FSTR + c),        K_g + (size_t)(k0 + r) * HD + c);
            cp16(smem_u32(s + 4608 + r * FSTR + c), V_g + (size_t)(k0 + r) * HD + c);
        }
        cp_commit();
    };

    float o[8][4] = {};
    float m0 = -1e30f, m1 = -1e30f, l0 = 0.f, l1 = 0.f;
    const int row0g = q0 + w * 16 + (lane >> 2);
    const int row1g = row0g + 8;

    issueKV(0, 0);

    #pragma unroll 1
    for (int kt = 0; kt <= qb; kt++) {
        const int buf = kt & 1;
        if (kt < qb) { issueKV(kt + 1, buf ^ 1); cp_wait<1>(); }
        else         { cp_wait<0>(); }
        __syncthreads();
        __half* sK = fsm + buf * FSTAGE;
        __half* sV = sK + 4608;

        float s[8][4] = {};
        #pragma unroll
        for (int kk = 0; kk < 4; kk++) {
            #pragma unroll
            for (int jp = 0; jp < 4; jp++) {
                uint32_t kb[4];
                int rT = jp * 16 + laneRowA;
                int cD = kk * 16 + laneColA;
                ldsm_x4(kb, smem_u32(sK + rT * FSTR + cD));
                mma_f16(s[jp * 2 + 0], qf[kk], kb[0], kb[2]);
                mma_f16(s[jp * 2 + 1], qf[kk], kb[1], kb[3]);
            }
        }

        if (kt == qb) {
            const int k0 = kt * 64;
            #pragma unroll
            for (int j = 0; j < 8; j++) {
                int colb = k0 + j * 8 + (lane & 3) * 2;
                if (colb > row0g)     s[j][0] = -1e30f;
                if (colb + 1 > row0g) s[j][1] = -1e30f;
                if (colb > row1g)     s[j][2] = -1e30f;
                if (colb + 1 > row1g) s[j][3] = -1e30f;
            }
        }

        float tmax0 = -1e30f, tmax1 = -1e30f;
        #pragma unroll
        for (int j = 0; j < 8; j++) {
            tmax0 = fmaxf(tmax0, fmaxf(s[j][0], s[j][1]));
            tmax1 = fmaxf(tmax1, fmaxf(s[j][2], s[j][3]));
        }
        tmax0 = fmaxf(tmax0, __shfl_xor_sync(0xffffffffu, tmax0, 1));
        tmax0 = fmaxf(tmax0, __shfl_xor_sync(0xffffffffu, tmax0, 2));
        tmax1 = fmaxf(tmax1, __shfl_xor_sync(0xffffffffu, tmax1, 1));
        tmax1 = fmaxf(tmax1, __shfl_xor_sync(0xffffffffu, tmax1, 2));
        float mn0 = fmaxf(m0, tmax0), mn1 = fmaxf(m1, tmax1);
        float al0 = __expf(m0 - mn0), al1 = __expf(m1 - mn1);
        m0 = mn0; m1 = mn1;
        float ps0 = 0.f, ps1 = 0.f;
        #pragma unroll
        for (int j = 0; j < 8; j++) {
            s[j][0] = __expf(s[j][0] - mn0);
            s[j][1] = __expf(s[j][1] - mn0);
            s[j][2] = __expf(s[j][2] - mn1);
            s[j][3] = __expf(s[j][3] - mn1);
            ps0 += s[j][0] + s[j][1];
            ps1 += s[j][2] + s[j][3];
        }
        l0 = l0 * al0 + ps0;
        l1 = l1 * al1 + ps1;
        #pragma unroll
        for (int j = 0; j < 8; j++) {
            o[j][0] *= al0; o[j][1] *= al0;
            o[j][2] *= al1; o[j][3] *= al1;
        }

        #pragma unroll
        for (int kk = 0; kk < 4; kk++) {
            uint32_t ap[4];
            ap[0] = pack_hf2(s[2*kk][0],   s[2*kk][1]);
            ap[1] = pack_hf2(s[2*kk][2],   s[2*kk][3]);
            ap[2] = pack_hf2(s[2*kk+1][0], s[2*kk+1][1]);
            ap[3] = pack_hf2(s[2*kk+1][2], s[2*kk+1][3]);
            #pragma unroll
            for (int jp = 0; jp < 4; jp++) {
                uint32_t vb[4];
                ldsm_x4t(vb, smem_u32(sV + (kk * 16 + lb16) * FSTR + jp * 16 + lbc));
                mma_f16(o[jp * 2 + 0], ap, vb[0], vb[1]);
                mma_f16(o[jp * 2 + 1], ap, vb[2], vb[3]);
            }
        }
        __syncthreads();
    }

    l0 += __shfl_xor_sync(0xffffffffu, l0, 1);
    l0 += __shfl_xor_sync(0xffffffffu, l0, 2);
    l1 += __shfl_xor_sync(0xffffffffu, l1, 1);
    l1 += __shfl_xor_sync(0xffffffffu, l1, 2);
    float inv0 = 1.f / l0, inv1 = 1.f / l1;

    const int b = bh >> 4, h = bh & 15;
    #pragma unroll
    for (int j = 0; j < 8; j++) {
        int col = h * HD + j * 8 + (lane & 3) * 2;
        {
            size_t idx = ((size_t)(b * Tt + row0g)) * Cc + col;
            *reinterpret_cast<__half2*>(&g_att[idx]) =
                __floats2half2_rn(o[j][0] * inv0, o[j][1] * inv0);
        }
        {
            size_t idx = ((size_t)(b * Tt + row1g)) * Cc + col;
            *reinterpret_cast<__half2*>(&g_att[idx]) =
                __floats2half2_rn(o[j][2] * inv1, o[j][3] * inv1);
        }
    }
}

// ---------------------------------------------------------------------------
extern "C" void kernel_launch(void* const* d_in, const int* in_sizes, int n_in,
                              void* d_out, int out_size) {
    const float* x        = (const float*)d_in[0];
    const float* ln_scale = (const float*)d_in[2];
    const float* ln_bias  = (const float*)d_in[3];
    const float* qkv_w    = (const float*)d_in[4];
    const float* qkv_b    = (const float*)d_in[5];
    const float* proj_w   = (const float*)d_in[6];
    const float* proj_b   = (const float*)d_in[7];
    float* out = (float*)d_out;

    const int gemm_smem  = STAGE_E * 3 * (int)sizeof(__half);   // 107520
    const int flash_smem = FSTAGE * 2 * (int)sizeof(__half);    // 36864

    static bool attr_set = false;
    if (!attr_set) {
        cudaFuncSetAttribute(flash_mma,
                             cudaFuncAttributeMaxDynamicSharedMemorySize, flash_smem);
        cudaFuncSetAttribute(mma_gemm<QKV_N, 0>,
                             cudaFuncAttributeMaxDynamicSharedMemorySize, gemm_smem);
        cudaFuncSetAttribute(mma_gemm<Cc, 1>,
                             cudaFuncAttributeMaxDynamicSharedMemorySize, gemm_smem);
        attr_set = true;
    }

    __half *xn, *wq, *wp, *att;
    cudaGetSymbolAddress((void**)&xn, g_xn);
    cudaGetSymbolAddress((void**)&wq, g_wq);
    cudaGetSymbolAddress((void**)&wp, g_wp);
    cudaGetSymbolAddress((void**)&att, g_att);

    ln_kernel<<<MROWS / 8, 256>>>(x, ln_scale, ln_bias);
    cvt_kernel<<<(Cc * QKV_N) / 1024, 256>>>(qkv_w, wq);
    cvt_kernel<<<(Cc * Cc) / 1024, 256>>>(proj_w, wp);

    mma_gemm<QKV_N, 0><<<dim3(QKV_N / 128, MROWS / 128), 256, gemm_smem>>>(
        xn, wq, qkv_b, nullptr);
    flash_mma<<<dim3(Tt / 64, Bb * NH), 128, flash_smem>>>();
    mma_gemm<Cc, 1><<<dim3(Cc / 128, MROWS / 128), 256, gemm_smem>>>(
        att, wp, proj_b, out);
}

// round 17
// speedup vs baseline: 1.0722x; 1.0722x over previous
#include <cuda_runtime.h>
#include <cuda_bf16.h>
#include <cuda_fp16.h>
#include <cstdint>
#include <math.h>

#define Bb 2
#define Tt 2048
#define Cc 1024
#define NH 16
#define HD 64
#define MROWS (Bb*Tt)          // 4096
#define QKV_N (3*Cc)           // 3072

// Scratch
__device__ __half g_xn  [MROWS*Cc];            // LN out single fp16
__device__ __half g_wq  [Cc*QKV_N];            // qkv W single fp16
__device__ __half g_wp  [Cc*Cc];               // proj W single fp16
__device__ __half g_q  [Bb*NH*Tt*HD];          // [b,h,t,d] single (scaled 1/8)
__device__ __half g_k  [Bb*NH*Tt*HD];          // [b,h,t,d] single
__device__ __half g_v  [Bb*NH*Tt*HD];          // [b,h,t,d] single
__device__ __half g_att[MROWS*Cc];             // attention out single fp16

__device__ __forceinline__ uint32_t smem_u32(const void* p) {
    return (uint32_t)__cvta_generic_to_shared(p);
}
__device__ __forceinline__ void cp16(uint32_t dst, const void* src) {
    asm volatile("cp.async.ca.shared.global [%0], [%1], 16;\n" :: "r"(dst), "l"(src));
}
__device__ __forceinline__ void cp_commit() { asm volatile("cp.async.commit_group;\n"); }
template<int N> __device__ __forceinline__ void cp_wait() {
    asm volatile("cp.async.wait_group %0;\n" :: "n"(N));
}
__device__ __forceinline__ void ldsm_x4(uint32_t a[4], uint32_t addr) {
    asm volatile("ldmatrix.sync.aligned.m8n8.x4.shared.b16 {%0,%1,%2,%3}, [%4];"
                 : "=r"(a[0]),"=r"(a[1]),"=r"(a[2]),"=r"(a[3]) : "r"(addr));
}
__device__ __forceinline__ void ldsm_x4t(uint32_t b[4], uint32_t addr) {
    asm volatile("ldmatrix.sync.aligned.m8n8.x4.trans.shared.b16 {%0,%1,%2,%3}, [%4];"
                 : "=r"(b[0]),"=r"(b[1]),"=r"(b[2]),"=r"(b[3]) : "r"(addr));
}
__device__ __forceinline__ void mma_f16(float c[4], const uint32_t a[4], const uint32_t b0, const uint32_t b1) {
    asm volatile("mma.sync.aligned.m16n8k16.row.col.f32.f16.f16.f32 "
        "{%0,%1,%2,%3}, {%4,%5,%6,%7}, {%8,%9}, {%0,%1,%2,%3};"
        : "+f"(c[0]),"+f"(c[1]),"+f"(c[2]),"+f"(c[3])
        : "r"(a[0]),"r"(a[1]),"r"(a[2]),"r"(a[3]), "r"(b0),"r"(b1));
}
__device__ __forceinline__ uint32_t pack_hf2(float x, float y) {
    __half2 t = __floats2half2_rn(x, y);
    return *reinterpret_cast<uint32_t*>(&t);
}

// ---------------------------------------------------------------------------
// LayerNorm, warp-per-row: 8 rows per 256-thread block.
// ---------------------------------------------------------------------------
__global__ __launch_bounds__(256) void ln_kernel(
    const float* __restrict__ x, const float* __restrict__ scale,
    const float* __restrict__ bias) {
    const int w = threadIdx.x >> 5, lane = threadIdx.x & 31;
    const int row = blockIdx.x * 8 + w;
    const float* xr = x + (size_t)row * Cc;

    float v[32];
    #pragma unroll
    for (int i = 0; i < 8; i++) {
        float4 t = *reinterpret_cast<const float4*>(xr + i * 128 + lane * 4);
        v[i*4+0] = t.x; v[i*4+1] = t.y; v[i*4+2] = t.z; v[i*4+3] = t.w;
    }
    float s = 0.f;
    #pragma unroll
    for (int i = 0; i < 32; i++) s += v[i];
    #pragma unroll
    for (int o = 16; o > 0; o >>= 1) s += __shfl_xor_sync(0xffffffffu, s, o);
    float mu = s * (1.f / Cc);
    float sq = 0.f;
    #pragma unroll
    for (int i = 0; i < 32; i++) { float d = v[i] - mu; sq += d * d; }
    #pragma unroll
    for (int o = 16; o > 0; o >>= 1) sq += __shfl_xor_sync(0xffffffffu, sq, o);
    float inv = rsqrtf(sq * (1.f / Cc) + 1e-6f);

    #pragma unroll
    for (int i = 0; i < 8; i++) {
        int col = i * 128 + lane * 4;
        float4 sc = *reinterpret_cast<const float4*>(scale + col);
        float4 bi = *reinterpret_cast<const float4*>(bias + col);
        float o0 = (v[i*4+0] - mu) * inv * sc.x + bi.x;
        float o1 = (v[i*4+1] - mu) * inv * sc.y + bi.y;
        float o2 = (v[i*4+2] - mu) * inv * sc.z + bi.z;
        float o3 = (v[i*4+3] - mu) * inv * sc.w + bi.w;
        uint2 pk;
        pk.x = pack_hf2(o0, o1);
        pk.y = pack_hf2(o2, o3);
        *reinterpret_cast<uint2*>(&g_xn[(size_t)row * Cc + col]) = pk;
    }
}

// ---------------------------------------------------------------------------
// Fused weight convert: first NQ elems -> wq, rest -> wp.
// ---------------------------------------------------------------------------
__global__ __launch_bounds__(256) void cvt2_kernel(
    const float* __restrict__ srcq, const float* __restrict__ srcp,
    __half* __restrict__ dq, __half* __restrict__ dp, int nq) {
    int i = (blockIdx.x * 256 + threadIdx.x) * 4;
    const float* src;
    __half* dst;
    int off;
    if (i < nq) { src = srcq; dst = dq; off = i; }
    else        { src = srcp; dst = dp; off = i - nq; }
    float4 v = *reinterpret_cast<const float4*>(src + off);
    *reinterpret_cast<__half2*>(&dst[off])     = __floats2half2_rn(v.x, v.y);
    *reinterpret_cast<__half2*>(&dst[off + 2]) = __floats2half2_rn(v.z, v.w);
}

// ---------------------------------------------------------------------------
// fp16 single tensor-core GEMM: 128x128 block, BK=64, 2-stage (R15 exact).
// Stage: A[128][72]=9216 + B[64][136]=8704 = 17920 elems (35.8KB), 2 stages.
// ---------------------------------------------------------------------------
#define STAGE_E 17920
#define A_STR 72
#define B_STR 136

template<int ND, int EPI>
__global__ __launch_bounds__(256, 2) void mma_gemm(
    const __half* __restrict__ A_g, const __half* __restrict__ B_g,
    const float* __restrict__ bias, float* __restrict__ Cout)
{
    extern __shared__ __half smem[];
    const int tid = threadIdx.x;
    const int wid = tid >> 5, lane = tid & 31;
    const int wm = wid >> 2, wn = wid & 3;
    const int row0 = blockIdx.y * 128;
    const int col0 = blockIdx.x * 128;

    const int laneRowA = (lane & 7) + ((lane >> 3) & 1) * 8;
    const int laneColA = (lane >> 4) * 8;
    const int lb16 = lane & 15;
    const int lbc = (lane >> 4) * 8;

    auto issue = [&](int it, int stage) {
        const int k0 = it * 64;
        __half* s = smem + stage * STAGE_E;
        #pragma unroll
        for (int u = 0; u < 4; u++) {
            int c = tid + u * 256;
            int ar = c >> 3, ac = (c & 7) * 8;          // A: 128 rows x 8 chunks
            cp16(smem_u32(s + ar * A_STR + ac),
                 A_g + (size_t)(row0 + ar) * Cc + k0 + ac);
            int br = c >> 4, bc = (c & 15) * 8;         // B: 64 rows x 16 chunks
            cp16(smem_u32(s + 9216 + br * B_STR + bc),
                 B_g + (size_t)(k0 + br) * ND + col0 + bc);
        }
        cp_commit();
    };

    float acc[4][4][4] = {};
    issue(0, 0);

    #pragma unroll 1
    for (int it = 0; it < 16; it++) {
        const int buf = it & 1;
        if (it + 1 < 16) { issue(it + 1, buf ^ 1); cp_wait<1>(); }
        else             { cp_wait<0>(); }
        __syncthreads();
        __half* sA = smem + buf * STAGE_E;
        __half* sB = sA + 9216;
        #pragma unroll
        for (int kk = 0; kk < 4; kk++) {
            uint32_t aa[4][4], bb[2][4];
            #pragma unroll
            for (int i = 0; i < 4; i++) {
                int r = wm * 64 + i * 16 + laneRowA;
                int cA = kk * 16 + laneColA;
                ldsm_x4(aa[i], smem_u32(sA + r * A_STR + cA));
            }
            #pragma unroll
            for (int jp = 0; jp < 2; jp++) {
                int rB = kk * 16 + lb16;
                int cB = wn * 32 + jp * 16 + lbc;
                ldsm_x4t(bb[jp], smem_u32(sB + rB * B_STR + cB));
            }
            #pragma unroll
            for (int i = 0; i < 4; i++)
                #pragma unroll
                for (int j = 0; j < 4; j++)
                    mma_f16(acc[i][j], aa[i], bb[j >> 1][(j & 1) * 2],
                            bb[j >> 1][(j & 1) * 2 + 1]);
        }
        __syncthreads();
    }

    #pragma unroll
    for (int i = 0; i < 4; i++) {
        int rbase = row0 + wm * 64 + i * 16 + (lane >> 2);
        #pragma unroll
        for (int j = 0; j < 4; j++) {
            int nb = col0 + wn * 32 + j * 8 + (lane & 3) * 2;
            float v0 = acc[i][j][0] + bias[nb];
            float v1 = acc[i][j][1] + bias[nb + 1];
            float v2 = acc[i][j][2] + bias[nb];
            float v3 = acc[i][j][3] + bias[nb + 1];
            if (EPI == 1) {
                float2 p0 = {v0, v1}, p1 = {v2, v3};
                *reinterpret_cast<float2*>(&Cout[(size_t)rbase * Cc + nb]) = p0;
                *reinterpret_cast<float2*>(&Cout[(size_t)(rbase + 8) * Cc + nb]) = p1;
            } else {
                int b = rbase >> 11, t = rbase & 2047;
                int which = nb >> 10, rr = nb & 1023;
                int h = rr >> 6, d = rr & 63;
                float sc = (which == 0) ? 0.125f : 1.f;
                __half* dst = (which == 0) ? g_q : ((which == 1) ? g_k : g_v);
                size_t idx = (((size_t)(b * NH + h) * Tt) + t) * HD + d;
                *reinterpret_cast<__half2*>(&dst[idx]) =
                    __floats2half2_rn(v0 * sc, v1 * sc);
                *reinterpret_cast<__half2*>(&dst[idx + 8 * HD]) =
                    __floats2half2_rn(v2 * sc, v3 * sc);
            }
        }
    }
}

// ---------------------------------------------------------------------------
// Tensor-core causal flash attention, fp16, BQ=64, 128 threads (R12 exact).
// ---------------------------------------------------------------------------
#define FSTR 72
#define FSTAGE 9216

__global__ __launch_bounds__(128, 4) void flash_mma() {
    extern __shared__ __half fsm[];
    const int tid = threadIdx.x;
    const int w = tid >> 5, lane = tid & 31;
    const int qb = (int)gridDim.x - 1 - (int)blockIdx.x;
    const int bh = blockIdx.y;
    const int q0 = qb * 64;

    const __half* Q_g = g_q + (size_t)bh * Tt * HD;
    const __half* K_g = g_k + (size_t)bh * Tt * HD;
    const __half* V_g = g_v + (size_t)bh * Tt * HD;

    const int laneRowA = (lane & 7) + ((lane >> 3) & 1) * 8;
    const int laneColA = (lane >> 4) * 8;
    const int lb16 = lane & 15;
    const int lbc = (lane >> 4) * 8;

    {
        #pragma unroll
        for (int u = 0; u < 4; u++) {
            int idx = tid + u * 128;
            int r = idx >> 3, c = (idx & 7) * 8;
            cp16(smem_u32(fsm + r * FSTR + c), Q_g + (size_t)(q0 + r) * HD + c);
        }
        cp_commit();
        cp_wait<0>();
        __syncthreads();
    }
    uint32_t qf[4][4];
    #pragma unroll
    for (int kk = 0; kk < 4; kk++) {
        int r = w * 16 + laneRowA;
        int c = kk * 16 + laneColA;
        ldsm_x4(qf[kk], smem_u32(fsm + r * FSTR + c));
    }
    __syncthreads();

    auto issueKV = [&](int kt, int stage) {
        const int k0 = kt * 64;
        __half* s = fsm + stage * FSTAGE;
        #pragma unroll
        for (int u = 0; u < 4; u++) {
            int idx = tid + u * 128;
            int r = idx >> 3, c = (idx & 7) * 8;
            cp16(smem_u32(s + r * FSTR + c),        K_g + (size_t)(k0 + r) * HD + c);
            cp16(smem_u32(s + 4608 + r * FSTR + c), V_g + (size_t)(k0 + r) * HD + c);
        }
        cp_commit();
    };

    float o[8][4] = {};
    float m0 = -1e30f, m1 = -1e30f, l0 = 0.f, l1 = 0.f;
    const int row0g = q0 + w * 16 + (lane >> 2);
    const int row1g = row0g + 8;

    issueKV(0, 0);

    #pragma unroll 1
    for (int kt = 0; kt <= qb; kt++) {
        const int buf = kt & 1;
        if (kt < qb) { issueKV(kt + 1, buf ^ 1); cp_wait<1>(); }
        else         { cp_wait<0>(); }
        __syncthreads();
        __half* sK = fsm + buf * FSTAGE;
        __half* sV = sK + 4608;

        float s[8][4] = {};
        #pragma unroll
        for (int kk = 0; kk < 4; kk++) {
            #pragma unroll
            for (int jp = 0; jp < 4; jp++) {
                uint32_t kb[4];
                int rT = jp * 16 + laneRowA;
                int cD = kk * 16 + laneColA;
                ldsm_x4(kb, smem_u32(sK + rT * FSTR + cD));
                mma_f16(s[jp * 2 + 0], qf[kk], kb[0], kb[2]);
                mma_f16(s[jp * 2 + 1], qf[kk], kb[1], kb[3]);
            }
        }

        if (kt == qb) {
            const int k0 = kt * 64;
            #pragma unroll
            for (int j = 0; j < 8; j++) {
                int colb = k0 + j * 8 + (lane & 3) * 2;
                if (colb > row0g)     s[j][0] = -1e30f;
                if (colb + 1 > row0g) s[j][1] = -1e30f;
                if (colb > row1g)     s[j][2] = -1e30f;
                if (colb + 1 > row1g) s[j][3] = -1e30f;
            }
        }

        float tmax0 = -1e30f, tmax1 = -1e30f;
        #pragma unroll
        for (int j = 0; j < 8; j++) {
            tmax0 = fmaxf(tmax0, fmaxf(s[j][0], s[j][1]));
            tmax1 = fmaxf(tmax1, fmaxf(s[j][2], s[j][3]));
        }
        tmax0 = fmaxf(tmax0, __shfl_xor_sync(0xffffffffu, tmax0, 1));
        tmax0 = fmaxf(tmax0, __shfl_xor_sync(0xffffffffu, tmax0, 2));
        tmax1 = fmaxf(tmax1, __shfl_xor_sync(0xffffffffu, tmax1, 1));
        tmax1 = fmaxf(tmax1, __shfl_xor_sync(0xffffffffu, tmax1, 2));
        float mn0 = fmaxf(m0, tmax0), mn1 = fmaxf(m1, tmax1);
        float al0 = __expf(m0 - mn0), al1 = __expf(m1 - mn1);
        m0 = mn0; m1 = mn1;
        float ps0 = 0.f, ps1 = 0.f;
        #pragma unroll
        for (int j = 0; j < 8; j++) {
            s[j][0] = __expf(s[j][0] - mn0);
            s[j][1] = __expf(s[j][1] - mn0);
            s[j][2] = __expf(s[j][2] - mn1);
            s[j][3] = __expf(s[j][3] - mn1);
            ps0 += s[j][0] + s[j][1];
            ps1 += s[j][2] + s[j][3];
        }
        l0 = l0 * al0 + ps0;
        l1 = l1 * al1 + ps1;
        #pragma unroll
        for (int j = 0; j < 8; j++) {
            o[j][0] *= al0; o[j][1] *= al0;
            o[j][2] *= al1; o[j][3] *= al1;
        }

        #pragma unroll
        for (int kk = 0; kk < 4; kk++) {
            uint32_t ap[4];
            ap[0] = pack_hf2(s[2*kk][0],   s[2*kk][1]);
            ap[1] = pack_hf2(s[2*kk][2],   s[2*kk][3]);
            ap[2] = pack_hf2(s[2*kk+1][0], s[2*kk+1][1]);
            ap[3] = pack_hf2(s[2*kk+1][2], s[2*kk+1][3]);
            #pragma unroll
            for (int jp = 0; jp < 4; jp++) {
                uint32_t vb[4];
                ldsm_x4t(vb, smem_u32(sV + (kk * 16 + lb16) * FSTR + jp * 16 + lbc));
                mma_f16(o[jp * 2 + 0], ap, vb[0], vb[1]);
                mma_f16(o[jp * 2 + 1], ap, vb[2], vb[3]);
            }
        }
        __syncthreads();
    }

    l0 += __shfl_xor_sync(0xffffffffu, l0, 1);
    l0 += __shfl_xor_sync(0xffffffffu, l0, 2);
    l1 += __shfl_xor_sync(0xffffffffu, l1, 1);
    l1 += __shfl_xor_sync(0xffffffffu, l1, 2);
    float inv0 = 1.f / l0, inv1 = 1.f / l1;

    const int b = bh >> 4, h = bh & 15;
    #pragma unroll
    for (int j = 0; j < 8; j++) {
        int col = h * HD + j * 8 + (lane & 3) * 2;
        {
            size_t idx = ((size_t)(b * Tt + row0g)) * Cc + col;
            *reinterpret_cast<__half2*>(&g_att[idx]) =
                __floats2half2_rn(o[j][0] * inv0, o[j][1] * inv0);
        }
        {
            size_t idx = ((size_t)(b * Tt + row1g)) * Cc + col;
            *reinterpret_cast<__half2*>(&g_att[idx]) =
                __floats2half2_rn(o[j][2] * inv1, o[j][3] * inv1);
        }
    }
}

// ---------------------------------------------------------------------------
extern "C" void kernel_launch(void* const* d_in, const int* in_sizes, int n_in,
                              void* d_out, int out_size) {
    const float* x        = (const float*)d_in[0];
    const float* ln_scale = (const float*)d_in[2];
    const float* ln_bias  = (const float*)d_in[3];
    const float* qkv_w    = (const float*)d_in[4];
    const float* qkv_b    = (const float*)d_in[5];
    const float* proj_w   = (const float*)d_in[6];
    const float* proj_b   = (const float*)d_in[7];
    float* out = (float*)d_out;

    const int gemm_smem  = STAGE_E * 2 * (int)sizeof(__half);   // 71680
    const int flash_smem = FSTAGE * 2 * (int)sizeof(__half);    // 36864

    static bool attr_set = false;
    if (!attr_set) {
        cudaFuncSetAttribute(flash_mma,
                             cudaFuncAttributeMaxDynamicSharedMemorySize, flash_smem);
        cudaFuncSetAttribute(mma_gemm<QKV_N, 0>,
                             cudaFuncAttributeMaxDynamicSharedMemorySize, gemm_smem);
        cudaFuncSetAttribute(mma_gemm<Cc, 1>,
                             cudaFuncAttributeMaxDynamicSharedMemorySize, gemm_smem);
        attr_set = true;
    }

    __half *xn, *wq, *wp, *att;
    cudaGetSymbolAddress((void**)&xn, g_xn);
    cudaGetSymbolAddress((void**)&wq, g_wq);
    cudaGetSymbolAddress((void**)&wp, g_wp);
    cudaGetSymbolAddress((void**)&att, g_att);

    ln_kernel<<<MROWS / 8, 256>>>(x, ln_scale, ln_bias);
    cvt2_kernel<<<(Cc * QKV_N + Cc * Cc) / 1024, 256>>>(
        qkv_w, proj_w, wq, wp, Cc * QKV_N);

    mma_gemm<QKV_N, 0><<<dim3(QKV_N / 128, MROWS / 128), 256, gemm_smem>>>(
        xn, wq, qkv_b, nullptr);
    flash_mma<<<dim3(Tt / 64, Bb * NH), 128, flash_smem>>>();
    mma_gemm<Cc, 1><<<dim3(Cc / 128, MROWS / 128), 256, gemm_smem>>>(
        att, wp, proj_b, out);
}